// round 9
// baseline (speedup 1.0000x reference)
#include <cuda_runtime.h>
#include <cuda_fp16.h>
#include <cstdint>
#include <math.h>

#define BS   32768
#define NQ   8
#define FFN  2048
#define EMB  512

#define TMT  128              // tokens per CTA (GEMM)
#define TNT  128              // out cols per CTA
#define KC   64               // FFN chunk per iteration (4 x k16 mma steps)
#define NC   (FFN / KC)       // 32 iterations
#define NTH  128              // 4 warps, 2x2 grid of 64x64 warp tiles
#define ROWB 144              // 128B data + 16B pad -> ldmatrix conflict-free

// scratch: H fp16 [BS][FFN], W2 transposed fp16 [EMB][FFN]
__device__ __half g_h[BS * FFN];
__device__ __half g_w2t[EMB * FFN];

// ---- smem: 3 stages x (A 128x144 + B 128x144) = 108 KB ----
#define SM_A(s)  ((s) * 36864)
#define SM_B(s)  ((s) * 36864 + 18432)
#define SMEM_BYTES 110592

__device__ __forceinline__ uint32_t smem_u32(const void* p) {
    uint32_t a;
    asm("{ .reg .u64 t; cvta.to.shared.u64 t, %1; cvt.u32.u64 %0, t; }" : "=r"(a) : "l"(p));
    return a;
}

#define LDSM4(r, a)                                                            \
    asm volatile("ldmatrix.sync.aligned.m8n8.x4.shared.b16 {%0,%1,%2,%3}, [%4];" \
        : "=r"((r)[0]), "=r"((r)[1]), "=r"((r)[2]), "=r"((r)[3]) : "r"(a))

#define MMAF16(d, a, b0, b1v)                                                  \
    asm volatile("mma.sync.aligned.m16n8k16.row.col.f32.f16.f16.f32 "         \
        "{%0,%1,%2,%3},{%4,%5,%6,%7},{%8,%9},{%0,%1,%2,%3};"                  \
        : "+f"((d)[0]), "+f"((d)[1]), "+f"((d)[2]), "+f"((d)[3])              \
        : "r"((a)[0]), "r"((a)[1]), "r"((a)[2]), "r"((a)[3]), "r"(b0), "r"(b1v))

#define CP16(dst, src)                                                         \
    asm volatile("cp.async.cg.shared.global [%0], [%1], 16;" :: "r"(dst), "l"(src))
#define CP_COMMIT() asm volatile("cp.async.commit_group;" ::: "memory")
#define CP_WAIT1()  asm volatile("cp.async.wait_group 1;" ::: "memory")

// ---- pre kernel: W2 transpose/convert (blocks < 4096) + H (blocks >= 4096) --
// launch_bounds(256,2): 128 regs -> h's W1 slice stays register-resident.
#define TB 64
#define PREP_BLOCKS (EMB * FFN / 256)      // 4096
__global__ __launch_bounds__(256, 2)
void pre_kernel(const float* __restrict__ x,
                const float* __restrict__ theta,
                const float* __restrict__ W1,
                const float* __restrict__ b1,
                const float* __restrict__ W2)
{
    const int tid = threadIdx.x;

    if (blockIdx.x < PREP_BLOCKS) {
        int t = blockIdx.x * 256 + tid;
        int n = t >> 11;
        int k = t & (FFN - 1);
        g_w2t[t] = __float2half_rn(W2[(size_t)k * EMB + n]);
        return;
    }

    __shared__ float q_s[TB][NQ];
    const int row0 = (blockIdx.x - PREP_BLOCKS) * TB;
    const int k0   = tid * 8;

    #pragma unroll
    for (int i = tid; i < TB * NQ; i += 256) {
        int m = i >> 3, j = i & 7;
        q_s[m][j] = cosf(x[(size_t)(row0 + m) * NQ + j]) * cosf(__ldg(&theta[j]));
    }

    float w1r[8][NQ];
    float b1r[8];
    #pragma unroll
    for (int u = 0; u < 8; u++) {
        b1r[u] = __ldg(&b1[k0 + u]);
        #pragma unroll
        for (int j = 0; j < NQ; j++)
            w1r[u][j] = __ldg(&W1[(size_t)j * FFN + k0 + u]);
    }
    __syncthreads();

    for (int t = 0; t < TB; t++) {
        float4 qa = *(const float4*)&q_s[t][0];
        float4 qb = *(const float4*)&q_s[t][4];
        uint32_t w[4];
        #pragma unroll
        for (int u = 0; u < 8; u++) {
            float s = b1r[u];
            s = fmaf(qa.x, w1r[u][0], s); s = fmaf(qa.y, w1r[u][1], s);
            s = fmaf(qa.z, w1r[u][2], s); s = fmaf(qa.w, w1r[u][3], s);
            s = fmaf(qb.x, w1r[u][4], s); s = fmaf(qb.y, w1r[u][5], s);
            s = fmaf(qb.z, w1r[u][6], s); s = fmaf(qb.w, w1r[u][7], s);
            s = fmaxf(s, 0.f);
            uint32_t hb = (uint32_t)__half_as_ushort(__float2half_rn(s));
            if (u & 1) w[u >> 1] |= hb << 16;
            else       w[u >> 1]  = hb;
        }
        *(uint4*)((char*)(g_h + (size_t)(row0 + t) * FFN) + tid * 16)
            = make_uint4(w[0], w[1], w[2], w[3]);
    }
}

// ---- gemm: out = H @ W2 + b2, fp16 MMA / fp32 accum, 64x64 warp tiles ------
// 3-stage cp.async pipeline, software-pipelined LDSM fragments, occ 2.
__global__ __launch_bounds__(NTH, 2)
void gemm_kernel(const float* __restrict__ b2, float* __restrict__ out)
{
    extern __shared__ char sm[];
    const uint32_t smb = smem_u32(sm);

    const int tid  = threadIdx.x;
    const int wid  = tid >> 5;
    const int lane = tid & 31;
    const int col0 = blockIdx.x * TNT;      // x fastest: 4 col CTAs share A via L2
    const int row0 = blockIdx.y * TMT;
    const int wm   = wid & 1;               // 2 M groups of 64 rows
    const int wn   = wid >> 1;              // 2 N groups of 64 cols

    const uint32_t a_off = (uint32_t)(wm * 64 + (lane & 15)) * ROWB + ((lane >> 4) << 4);
    const uint32_t b_off = (uint32_t)(wn * 64 + (lane & 7) + ((lane & 16) >> 1)) * ROWB
                         + ((lane & 8) << 1);

    // cp.async: thread covers row = tid>>3 (+16*r), 16B segment = tid&7
    const int ldr = tid >> 3;
    const int seg = (tid & 7) * 16;
    const char* gA = (const char*)(g_h   + (size_t)(row0 + ldr) * FFN) + seg;
    const char* gB = (const char*)(g_w2t + (size_t)(col0 + ldr) * FFN) + seg;
    const uint32_t soA = (uint32_t)ldr * ROWB + seg;

    auto issue = [&](int chunk, int s) {
        const char* a = gA + chunk * (KC * 2);
        const char* b = gB + chunk * (KC * 2);
        #pragma unroll
        for (int r = 0; r < 8; r++) {       // rows ldr + 16*r
            CP16(smb + SM_A(s) + soA + r * 16 * ROWB, a + (size_t)r * 16 * FFN * 2);
            CP16(smb + SM_B(s) + soA + r * 16 * ROWB, b + (size_t)r * 16 * FFN * 2);
        }
    };

    float acc[4][8][4];
    #pragma unroll
    for (int a = 0; a < 4; a++)
        #pragma unroll
        for (int b = 0; b < 8; b++)
            #pragma unroll
            for (int i = 0; i < 4; i++) acc[a][b][i] = 0.f;

    // prologue: chunks 0 and 1 in flight (one group each)
    issue(0, 0); CP_COMMIT();
    issue(1, 1); CP_COMMIT();

    for (int c = 0; c < NC; c++) {
        const int s = c % 3;

        CP_WAIT1();             // chunk c landed; chunk c+1 still in flight
        __syncthreads();        // also: stage (c+2)%3 fully consumed (iter c-1)

        // prefetch chunk c+2 immediately -> overlaps with the whole consume
        if (c + 2 < NC) issue(c + 2, (c + 2) % 3);
        CP_COMMIT();

        const uint32_t A = smb + SM_A(s) + a_off;
        const uint32_t B = smb + SM_B(s) + b_off;

        // software-pipelined fragments: preload ks+1 while MMAing ks
        uint32_t ah[2][4][4], bh[2][4][4];
        #pragma unroll
        for (int mt = 0; mt < 4; mt++) LDSM4(ah[0][mt], A + mt * 16 * ROWB);
        #pragma unroll
        for (int g = 0; g < 4; g++)    LDSM4(bh[0][g], B + g * 16 * ROWB);

        #pragma unroll
        for (int ks = 0; ks < 4; ks++) {
            const int cur = ks & 1, nxt = cur ^ 1;
            if (ks < 3) {
                #pragma unroll
                for (int mt = 0; mt < 4; mt++)
                    LDSM4(ah[nxt][mt], A + mt * 16 * ROWB + (ks + 1) * 32);
                #pragma unroll
                for (int g = 0; g < 4; g++)
                    LDSM4(bh[nxt][g], B + g * 16 * ROWB + (ks + 1) * 32);
            }
            #pragma unroll
            for (int g = 0; g < 4; g++) {
                #pragma unroll
                for (int mt = 0; mt < 4; mt++) {
                    MMAF16(acc[mt][2 * g],     ah[cur][mt], bh[cur][g][0], bh[cur][g][1]);
                    MMAF16(acc[mt][2 * g + 1], ah[cur][mt], bh[cur][g][2], bh[cur][g][3]);
                }
            }
        }
        // no trailing barrier: 3 stages guarantee prefetch target is free
    }

    // epilogue: D frags + b2
    #pragma unroll
    for (int mt = 0; mt < 4; mt++) {
        int mrow = row0 + wm * 64 + mt * 16 + (lane >> 2);
        #pragma unroll
        for (int nt = 0; nt < 8; nt++) {
            int ncol = col0 + wn * 64 + nt * 8 + (lane & 3) * 2;
            float bx = b2[ncol], by = b2[ncol + 1];
            float2 v0 = make_float2(acc[mt][nt][0] + bx, acc[mt][nt][1] + by);
            float2 v1 = make_float2(acc[mt][nt][2] + bx, acc[mt][nt][3] + by);
            *(float2*)&out[(size_t)mrow * EMB + ncol]       = v0;
            *(float2*)&out[(size_t)(mrow + 8) * EMB + ncol] = v1;
        }
    }
}

// ---- launcher ----------------------------------------------------------------
extern "C" void kernel_launch(void* const* d_in, const int* in_sizes, int n_in,
                              void* d_out, int out_size)
{
    const float *x = 0, *theta = 0, *W1 = 0, *b1 = 0, *W2 = 0, *b2 = 0;
    for (int i = 0; i < n_in; i++) {
        switch (in_sizes[i]) {
            case BS * NQ:   x     = (const float*)d_in[i]; break;
            case NQ:        theta = (const float*)d_in[i]; break;
            case NQ * FFN:  W1    = (const float*)d_in[i]; break;
            case FFN:       b1    = (const float*)d_in[i]; break;
            case FFN * EMB: W2    = (const float*)d_in[i]; break;
            case EMB:       b2    = (const float*)d_in[i]; break;
            default: break;
        }
    }

    pre_kernel<<<PREP_BLOCKS + BS / TB, 256>>>(x, theta, W1, b1, W2);

    cudaFuncSetAttribute(gemm_kernel, cudaFuncAttributeMaxDynamicSharedMemorySize,
                         SMEM_BYTES);
    dim3 grid(EMB / TNT, BS / TMT);   // 4 x 256; col-fastest for L2 A reuse
    gemm_kernel<<<grid, NTH, SMEM_BYTES>>>(b2, (float*)d_out);
}